// round 1
// baseline (speedup 1.0000x reference)
#include <cuda_runtime.h>

#define N_PTS   131072
#define K_CB    1024
#define D_DIM   10
#define ROW     12          // padded floats per codebook row: 10 dims + esq + pad0
#define THREADS 256
#define PPT     2           // points per thread
#define NBLOCKS (N_PTS / (THREADS * PPT))   // 256
#define NWARPS_TOTAL (NBLOCKS * (THREADS / 32))  // 2048

// deterministic loss partials (one per warp)
__device__ float g_partials[NWARPS_TOTAL];

__device__ __forceinline__ unsigned long long fma_f32x2(
    unsigned long long a, unsigned long long b, unsigned long long c) {
    unsigned long long d;
    asm("fma.rn.f32x2 %0, %1, %2, %3;" : "=l"(d) : "l"(a), "l"(b), "l"(c));
    return d;
}

__device__ __forceinline__ unsigned long long pack_f32x2(float lo, float hi) {
    unsigned long long r;
    asm("mov.b64 %0, {%1, %2};" : "=l"(r) : "f"(lo), "f"(hi));
    return r;
}

__device__ __forceinline__ float hsum_f32x2(unsigned long long v) {
    float lo, hi;
    asm("mov.b64 {%0, %1}, %2;" : "=f"(lo), "=f"(hi) : "l"(v));
    return lo + hi;
}

__global__ void __launch_bounds__(THREADS)
vq_kernel(const float* __restrict__ x,      // [N, D]
          const float* __restrict__ E,      // [K, D]
          float* __restrict__ out)          // [N*D] quantized (+ loss slot appended)
{
    __shared__ float sEf[K_CB * ROW];       // 49152 bytes exactly

    const int tid = threadIdx.x;

    // --- cooperative codebook load into padded shared layout ---
    for (int i = tid; i < K_CB * D_DIM; i += THREADS) {
        int r = i / D_DIM;
        int c = i - r * D_DIM;
        sEf[r * ROW + c] = E[i];
    }
    __syncthreads();
    // --- per-row ||e||^2 in slot 10, zero pad in slot 11 ---
    for (int r = tid; r < K_CB; r += THREADS) {
        float s = 0.f;
        #pragma unroll
        for (int j = 0; j < D_DIM; j++) {
            float v = sEf[r * ROW + j];
            s += v * v;
        }
        sEf[r * ROW + 10] = s;
        sEf[r * ROW + 11] = 0.f;
    }
    __syncthreads();

    // --- this thread's two points ---
    const int n0 = blockIdx.x * (THREADS * PPT) + tid;
    const int n1 = n0 + THREADS;

    float xA[D_DIM], xB[D_DIM];
    const float* xpA = x + (size_t)n0 * D_DIM;
    const float* xpB = x + (size_t)n1 * D_DIM;
    #pragma unroll
    for (int j = 0; j < D_DIM; j++) { xA[j] = xpA[j]; xB[j] = xpB[j]; }

    // xs = -2*x packed as f32x2 pairs (dims 2p, 2p+1)
    unsigned long long xsA[5], xsB[5];
    #pragma unroll
    for (int p = 0; p < 5; p++) {
        xsA[p] = pack_f32x2(-2.f * xA[2 * p], -2.f * xA[2 * p + 1]);
        xsB[p] = pack_f32x2(-2.f * xB[2 * p], -2.f * xB[2 * p + 1]);
    }

    // --- argmin scan over codebook ---
    // dist(k) = ||e_k||^2 - 2 x.e_k  (x^2 term constant per point, dropped)
    float bestA = 3.402823466e+38f, bestB = 3.402823466e+38f;
    int biA = 0, biB = 0;

    const ulonglong2* sp = (const ulonglong2*)sEf;  // 3 x ulonglong2 per row

    #pragma unroll 2
    for (int k = 0; k < K_CB; k++) {
        ulonglong2 v0 = sp[0];
        ulonglong2 v1 = sp[1];
        ulonglong2 v2 = sp[2];   // v2.y = (esq, 0.0f) in lanes (lo, hi)
        sp += 3;

        unsigned long long accA = v2.y;
        accA = fma_f32x2(v0.x, xsA[0], accA);
        accA = fma_f32x2(v0.y, xsA[1], accA);
        accA = fma_f32x2(v1.x, xsA[2], accA);
        accA = fma_f32x2(v1.y, xsA[3], accA);
        accA = fma_f32x2(v2.x, xsA[4], accA);
        float dA = hsum_f32x2(accA);

        unsigned long long accB = v2.y;
        accB = fma_f32x2(v0.x, xsB[0], accB);
        accB = fma_f32x2(v0.y, xsB[1], accB);
        accB = fma_f32x2(v1.x, xsB[2], accB);
        accB = fma_f32x2(v1.y, xsB[3], accB);
        accB = fma_f32x2(v2.x, xsB[4], accB);
        float dB = hsum_f32x2(accB);

        bool ltA = dA < bestA;
        biA = ltA ? k : biA;
        bestA = ltA ? dA : bestA;

        bool ltB = dB < bestB;
        biB = ltB ? k : biB;
        bestB = ltB ? dB : bestB;
    }

    // --- write quantized rows + accumulate loss partial ---
    float part = 0.f;
    {
        const float* e = &sEf[biA * ROW];
        float* o = out + (size_t)n0 * D_DIM;
        #pragma unroll
        for (int j = 0; j < D_DIM; j++) {
            float q = e[j];
            o[j] = q;
            float d = xA[j] - q;
            part += d * d;
        }
    }
    {
        const float* e = &sEf[biB * ROW];
        float* o = out + (size_t)n1 * D_DIM;
        #pragma unroll
        for (int j = 0; j < D_DIM; j++) {
            float q = e[j];
            o[j] = q;
            float d = xB[j] - q;
            part += d * d;
        }
    }

    // deterministic warp reduction -> fixed slot
    #pragma unroll
    for (int off = 16; off > 0; off >>= 1)
        part += __shfl_down_sync(0xFFFFFFFFu, part, off);
    if ((tid & 31) == 0) {
        int gwarp = blockIdx.x * (THREADS / 32) + (tid >> 5);
        g_partials[gwarp] = part;
    }
}

__global__ void __launch_bounds__(256)
finalize_loss(float* __restrict__ out)
{
    __shared__ float sh[256];
    float s = 0.f;
    for (int i = threadIdx.x; i < NWARPS_TOTAL; i += 256)
        s += g_partials[i];
    sh[threadIdx.x] = s;
    __syncthreads();
    #pragma unroll
    for (int o = 128; o > 0; o >>= 1) {
        if (threadIdx.x < o) sh[threadIdx.x] += sh[threadIdx.x + o];
        __syncthreads();
    }
    if (threadIdx.x == 0)
        out[(size_t)N_PTS * D_DIM] = sh[0] * (1.0f / ((float)N_PTS * (float)D_DIM));
}

extern "C" void kernel_launch(void* const* d_in, const int* in_sizes, int n_in,
                              void* d_out, int out_size) {
    const float* x = (const float*)d_in[0];   // encoder_embedding [N, D]
    const float* E = (const float*)d_in[1];   // embedding_weight  [K, D]
    float* out = (float*)d_out;

    vq_kernel<<<NBLOCKS, THREADS>>>(x, E, out);
    finalize_loss<<<1, 256>>>(out);
}

// round 2
// speedup vs baseline: 1.1359x; 1.1359x over previous
#include <cuda_runtime.h>

#define N_PTS   131072
#define K_CB    1024
#define NPAIR   512          // K_CB / 2
#define D_DIM   10
#define PROW    24           // floats per code-pair row: 10 dims x f32x2 + esq pair + pad = 12 x f32x2
#define THREADS 128
#define PPT     2
#define NBLOCKS (N_PTS / (THREADS * PPT))   // 512

__device__ float        g_partials[NBLOCKS];
__device__ unsigned int g_done = 0;

__device__ __forceinline__ unsigned long long fma2(
    unsigned long long a, unsigned long long b, unsigned long long c) {
    unsigned long long d;
    asm("fma.rn.f32x2 %0, %1, %2, %3;" : "=l"(d) : "l"(a), "l"(b), "l"(c));
    return d;
}
__device__ __forceinline__ unsigned long long dup2(float v) {
    unsigned long long r;
    asm("mov.b64 %0, {%1, %1};" : "=l"(r) : "f"(v));
    return r;
}
__device__ __forceinline__ void unpack2(unsigned long long v, float& lo, float& hi) {
    asm("mov.b64 {%0, %1}, %2;" : "=f"(lo), "=f"(hi) : "l"(v));
}

// Bit-exact distance pair for one code-pair row (identical FMA chain to the hot loop).
__device__ __forceinline__ void pair_dists(const ulonglong2* q,
                                           const unsigned long long* xd,
                                           float& d0, float& d1) {
    ulonglong2 w0 = q[0], w1 = q[1], w2 = q[2], w3 = q[3], w4 = q[4], w5 = q[5];
    unsigned long long a = w5.x;               // (esq0, esq1)
    a = fma2(w0.x, xd[0], a);
    a = fma2(w0.y, xd[1], a);
    a = fma2(w1.x, xd[2], a);
    a = fma2(w1.y, xd[3], a);
    a = fma2(w2.x, xd[4], a);
    a = fma2(w2.y, xd[5], a);
    a = fma2(w3.x, xd[6], a);
    a = fma2(w3.y, xd[7], a);
    a = fma2(w4.x, xd[8], a);
    a = fma2(w4.y, xd[9], a);
    unpack2(a, d0, d1);
}

__global__ void __launch_bounds__(THREADS, 4)
vq_kernel(const float* __restrict__ x,      // [N, D]
          const float* __restrict__ E,      // [K, D]
          float* __restrict__ out)          // [N*D] quantized + loss slot
{
    __shared__ float sE[NPAIR * PROW];      // 49152 bytes
    __shared__ float sred[THREADS / 32];
    __shared__ int   s_last;

    const int tid = threadIdx.x;

    // --- codebook -> pair-packed shared layout ---
    // sE[p*24 + 2*j + l] = E[(2p+l)*10 + j]
    for (int i = tid; i < K_CB * D_DIM; i += THREADS) {
        int k = i / D_DIM;
        int j = i - k * D_DIM;
        int p = k >> 1, l = k & 1;
        sE[p * PROW + 2 * j + l] = E[i];
    }
    __syncthreads();
    // esq into slots 20 (lane0) / 21 (lane1); zero pad 22/23
    for (int k = tid; k < K_CB; k += THREADS) {
        int p = k >> 1, l = k & 1;
        float s = 0.f;
        #pragma unroll
        for (int j = 0; j < D_DIM; j++) {
            float v = sE[p * PROW + 2 * j + l];
            s += v * v;
        }
        sE[p * PROW + 20 + l] = s;
        if (l == 0) { sE[p * PROW + 22] = 0.f; sE[p * PROW + 23] = 0.f; }
    }
    __syncthreads();

    // --- this thread's two points ---
    const int n0 = blockIdx.x * (THREADS * PPT) + tid;
    const int n1 = n0 + THREADS;

    unsigned long long xdA[D_DIM], xdB[D_DIM];
    {
        const float* xpA = x + (size_t)n0 * D_DIM;
        const float* xpB = x + (size_t)n1 * D_DIM;
        #pragma unroll
        for (int j = 0; j < D_DIM; j++) {
            xdA[j] = dup2(-2.f * xpA[j]);
            xdB[j] = dup2(-2.f * xpB[j]);
        }
    }

    // --- argmin scan: 2 codes per iter via f32x2 lanes, deferred lane pick ---
    float bestA = 3.402823466e+38f, bestB = 3.402823466e+38f;
    int bpA = 0, bpB = 0;

    const ulonglong2* sp = (const ulonglong2*)sE;   // 6 x ulonglong2 per pair row

    #pragma unroll 2
    for (int p = 0; p < NPAIR; ++p) {
        ulonglong2 w0 = sp[0], w1 = sp[1], w2 = sp[2];
        ulonglong2 w3 = sp[3], w4 = sp[4], w5 = sp[5];
        sp += 6;

        unsigned long long aA = w5.x;
        aA = fma2(w0.x, xdA[0], aA);
        aA = fma2(w0.y, xdA[1], aA);
        aA = fma2(w1.x, xdA[2], aA);
        aA = fma2(w1.y, xdA[3], aA);
        aA = fma2(w2.x, xdA[4], aA);
        aA = fma2(w2.y, xdA[5], aA);
        aA = fma2(w3.x, xdA[6], aA);
        aA = fma2(w3.y, xdA[7], aA);
        aA = fma2(w4.x, xdA[8], aA);
        aA = fma2(w4.y, xdA[9], aA);

        unsigned long long aB = w5.x;
        aB = fma2(w0.x, xdB[0], aB);
        aB = fma2(w0.y, xdB[1], aB);
        aB = fma2(w1.x, xdB[2], aB);
        aB = fma2(w1.y, xdB[3], aB);
        aB = fma2(w2.x, xdB[4], aB);
        aB = fma2(w2.y, xdB[5], aB);
        aB = fma2(w3.x, xdB[6], aB);
        aB = fma2(w3.y, xdB[7], aB);
        aB = fma2(w4.x, xdB[8], aB);
        aB = fma2(w4.y, xdB[9], aB);

        float d0A, d1A, d0B, d1B;
        unpack2(aA, d0A, d1A);
        unpack2(aB, d0B, d1B);

        float mA = fminf(d0A, d1A);             // FMNMX (alu pipe)
        if (mA < bestA) { bestA = mA; bpA = p; } // strict < keeps first min
        float mB = fminf(d0B, d1B);
        if (mB < bestB) { bestB = mB; bpB = p; }
    }

    // --- resolve winning lane (bit-exact recompute of one pair), write output ---
    float part = 0.f;
    {
        float d0, d1;
        pair_dists((const ulonglong2*)(sE + bpA * PROW), xdA, d0, d1);
        int lane = (d1 < d0) ? 1 : 0;           // tie -> lane 0 (lower k)
        const float* er = sE + bpA * PROW;
        const float* xr = x + (size_t)n0 * D_DIM;
        float* o = out + (size_t)n0 * D_DIM;
        #pragma unroll
        for (int j = 0; j < D_DIM; j++) {
            float q = er[2 * j + lane];
            o[j] = q;
            float dd = xr[j] - q;
            part += dd * dd;
        }
    }
    {
        float d0, d1;
        pair_dists((const ulonglong2*)(sE + bpB * PROW), xdB, d0, d1);
        int lane = (d1 < d0) ? 1 : 0;
        const float* er = sE + bpB * PROW;
        const float* xr = x + (size_t)n1 * D_DIM;
        float* o = out + (size_t)n1 * D_DIM;
        #pragma unroll
        for (int j = 0; j < D_DIM; j++) {
            float q = er[2 * j + lane];
            o[j] = q;
            float dd = xr[j] - q;
            part += dd * dd;
        }
    }

    // --- deterministic loss: warp reduce -> CTA reduce -> per-CTA partial ---
    #pragma unroll
    for (int off = 16; off > 0; off >>= 1)
        part += __shfl_down_sync(0xFFFFFFFFu, part, off);
    if ((tid & 31) == 0) sred[tid >> 5] = part;
    __syncthreads();

    if (tid == 0) {
        float s = sred[0] + sred[1] + sred[2] + sred[3];
        g_partials[blockIdx.x] = s;
        __threadfence();
        unsigned int old = atomicAdd(&g_done, 1u);
        s_last = (old == NBLOCKS - 1) ? 1 : 0;
    }
    __syncthreads();

    // --- last CTA finalizes the loss (fixed summation order -> deterministic) ---
    if (s_last) {
        float s = 0.f;
        #pragma unroll
        for (int r = 0; r < NBLOCKS / THREADS; r++)
            s += g_partials[r * THREADS + tid];
        sred[0] = 0.f;  // reuse pattern below avoids extra smem
        __syncthreads();
        // reduce 128 values deterministically via shared
        __shared__ float sfin[THREADS];
        sfin[tid] = s;
        __syncthreads();
        #pragma unroll
        for (int o = THREADS / 2; o > 0; o >>= 1) {
            if (tid < o) sfin[tid] += sfin[tid + o];
            __syncthreads();
        }
        if (tid == 0) {
            out[(size_t)N_PTS * D_DIM] = sfin[0] * (1.0f / ((float)N_PTS * (float)D_DIM));
            g_done = 0;   // reset for next graph replay
        }
    }
}

extern "C" void kernel_launch(void* const* d_in, const int* in_sizes, int n_in,
                              void* d_out, int out_size) {
    const float* x = (const float*)d_in[0];   // encoder_embedding [N, D]
    const float* E = (const float*)d_in[1];   // embedding_weight  [K, D]
    float* out = (float*)d_out;

    vq_kernel<<<NBLOCKS, THREADS>>>(x, E, out);
}